// round 16
// baseline (speedup 1.0000x reference)
#include <cuda_runtime.h>
#include <cuda_fp16.h>
#include <math.h>
#include <stdint.h>

// ---------------- problem dims ----------------
#define BB 256
#define LL 96
#define DD 512
#define HH 8
#define HDIM 64
#define DFF 2048
#define NT (BB*LL)          // 24576 tokens
#define SCALE 0.125f
#define EPS_LN 1e-5f
#define LOG2E 1.4426950408889634f

// ---------------- scratch (no allocs allowed) ----------------
__device__ __align__(16) __half g_src16[NT*DD];
__device__ __align__(16) __half g_q16 [NT*DD];
__device__ __align__(16) __half g_k16 [NT*DD];
__device__ __align__(16) __half g_v16 [NT*DD];
__device__ __align__(16) __half g_ao16[NT*DD];
__device__ __align__(16) __half g_x16 [NT*DD];
__device__ __align__(16) __half g_ff16[NT*DFF];
__device__ float g_t [NT*DD];
__device__ float g_x [NT*DD];
__device__ __align__(16) __half g_wt16[4*DD*DD + 2*DD*DFF];   // transposed fp16 weights

// offsets into g_wt16 (halves)
#define WT_Q  0
#define WT_K  (DD*DD)
#define WT_V  (2*DD*DD)
#define WT_O  (3*DD*DD)
#define WT_1  (4*DD*DD)            // W1T [2048,512]
#define WT_2  (4*DD*DD + DD*DFF)   // W2T [512,2048]

struct h4 { __half2 a, b; };

// ---------------- helpers ----------------
__device__ __forceinline__ void cp_async16(uint32_t dst, const void* src) {
    asm volatile("cp.async.cg.shared.global [%0], [%1], 16;" :: "r"(dst), "l"(src));
}
__device__ __forceinline__ void cp_commit() { asm volatile("cp.async.commit_group;" ::: "memory"); }
__device__ __forceinline__ void cp_wait1()  { asm volatile("cp.async.wait_group 1;" ::: "memory"); }

__device__ __forceinline__ void mma_f16(float* c, const uint32_t* a, const uint32_t* b) {
    asm volatile(
        "mma.sync.aligned.m16n8k16.row.col.f32.f16.f16.f32 "
        "{%0,%1,%2,%3}, {%4,%5,%6,%7}, {%8,%9}, {%0,%1,%2,%3};\n"
        : "+f"(c[0]), "+f"(c[1]), "+f"(c[2]), "+f"(c[3])
        : "r"(a[0]), "r"(a[1]), "r"(a[2]), "r"(a[3]), "r"(b[0]), "r"(b[1]));
}

__device__ __forceinline__ void ldsm_x4(uint32_t* r, uint32_t addr) {
    asm volatile("ldmatrix.sync.aligned.m8n8.x4.shared.b16 {%0,%1,%2,%3}, [%4];"
        : "=r"(r[0]), "=r"(r[1]), "=r"(r[2]), "=r"(r[3]) : "r"(addr));
}
__device__ __forceinline__ void ldsm_x2(uint32_t* r, uint32_t addr) {
    asm volatile("ldmatrix.sync.aligned.m8n8.x2.shared.b16 {%0,%1}, [%2];"
        : "=r"(r[0]), "=r"(r[1]) : "r"(addr));
}

__device__ __forceinline__ uint32_t h2ex2(uint32_t x) {
    uint32_t r;
    asm("ex2.approx.f16x2 %0, %1;" : "=r"(r) : "r"(x));
    return r;
}

__device__ __forceinline__ float gelu_exact(float x) {
    return 0.5f * x * (1.f + erff(x * 0.70710678118654752f));
}

// ---------------- fp16 MMA GEMM: 128x128 tile, BK=64, 3-stage cp.async + ldmatrix ----------------
#define STAGES 3
#define ROWB 144                       // 64 halves (128 B) + 16 B pad
#define A_ST (128*ROWB)                // 18432
#define B_ST (128*ROWB)
#define SMEM_GEMM (STAGES*(A_ST+B_ST)) // 110592 B

// EPI: 0 = bias -> fp16 out; 1 = bias+gelu -> fp16 out; 2 = bias+residual -> fp32 out
template<int EPI>
__device__ __forceinline__ void gemm_body(
    const __half* __restrict__ A, const __half* __restrict__ Bt,
    const float* __restrict__ bias, const float* __restrict__ resid,
    void* __restrict__ Cout, int N, int K, int bx, int by)
{
    extern __shared__ char smem[];
    const uint32_t smemA = (uint32_t)__cvta_generic_to_shared(smem);
    const uint32_t smemB = smemA + STAGES * A_ST;

    const int tid  = threadIdx.x;
    const int lane = tid & 31;
    const int wid  = tid >> 5;
    const int wm   = wid >> 2;
    const int wn   = wid & 3;
    const int lq   = lane & 3;
    const int lg   = lane >> 2;

    // ldmatrix x4 lane mapping: m0=rows0-7/c0, m1=rows8-15/c0, m2=rows0-7/c16, m3=rows8-15/c16
    const int lm_row = (lane & 7) | (((lane >> 3) & 1) << 3);
    const int lm_c16 = (lane >> 4) << 4;

    const __half* Ablk = A  + (size_t)by * 128 * K;
    const __half* Bblk = Bt + (size_t)bx * 128 * K;

    float acc[4][4][4];
    #pragma unroll
    for (int mt = 0; mt < 4; mt++)
        #pragma unroll
        for (int nt = 0; nt < 4; nt++)
            #pragma unroll
            for (int r = 0; r < 4; r++) acc[mt][nt][r] = 0.f;

    const int KT = K >> 6;    // K/64

    auto load_tile = [&](int kt) {
        const int s = kt % STAGES;
        const int kof = kt << 6;   // halves
        #pragma unroll
        for (int i = 0; i < 4; i++) {
            int c = tid + (i << 8);
            int r = c >> 3, cc = c & 7;
            cp_async16(smemA + s*A_ST + r*ROWB + cc*16, Ablk + (size_t)r * K + kof + cc*8);
            cp_async16(smemB + s*B_ST + r*ROWB + cc*16, Bblk + (size_t)r * K + kof + cc*8);
        }
    };

    // prologue: tiles 0,1
    load_tile(0); cp_commit();
    if (KT > 1) { load_tile(1); }
    cp_commit();

    const uint32_t a_lane_base = smemA + (wm * 64 + lm_row) * ROWB + lm_c16;
    const uint32_t b_lane_base = smemB + (wn * 32 + lm_row) * ROWB + lm_c16;

    for (int kt = 0; kt < KT; kt++) {
        cp_wait1();          // tile kt resident (<=1 group pending: kt+1)
        __syncthreads();

        int nk = kt + 2;
        if (nk < KT) load_tile(nk);
        cp_commit();

        const int s = kt % STAGES;
        const uint32_t abase = a_lane_base + s * A_ST;
        const uint32_t bbase = b_lane_base + s * B_ST;

        #pragma unroll
        for (int q0 = 0; q0 < 64; q0 += 16) {
            const int kb = 2 * q0;
            uint32_t af[4][4], b4[2][4];
            #pragma unroll
            for (int mt = 0; mt < 4; mt++)
                ldsm_x4(af[mt], abase + mt * 16 * ROWB + kb);
            #pragma unroll
            for (int n2 = 0; n2 < 2; n2++)
                ldsm_x4(b4[n2], bbase + n2 * 16 * ROWB + kb);
            // b4[n2]: r0 = n-rows 0-7 k0-7, r1 = n-rows 8-15 k0-7, r2 = n-rows 0-7 k8-15, r3 = n-rows 8-15 k8-15
            #pragma unroll
            for (int mt = 0; mt < 4; mt++) {
                #pragma unroll
                for (int n2 = 0; n2 < 2; n2++) {
                    uint32_t b0[2] = { b4[n2][0], b4[n2][2] };
                    uint32_t b1[2] = { b4[n2][1], b4[n2][3] };
                    mma_f16(acc[mt][2*n2],     af[mt], b0);
                    mma_f16(acc[mt][2*n2 + 1], af[mt], b1);
                }
            }
        }
    }

    #pragma unroll
    for (int mt = 0; mt < 4; mt++) {
        #pragma unroll
        for (int nt = 0; nt < 4; nt++) {
            int row = by * 128 + wm * 64 + mt * 16 + lg;
            int col = bx * 128 + wn * 32 + nt * 8 + 2 * lq;
            float2 bv = *reinterpret_cast<const float2*>(bias + col);
            #pragma unroll
            for (int half_i = 0; half_i < 2; half_i++) {
                int r = row + half_i * 8;
                float ox = acc[mt][nt][half_i * 2 + 0] + bv.x;
                float oy = acc[mt][nt][half_i * 2 + 1] + bv.y;
                if (EPI == 1) { ox = gelu_exact(ox); oy = gelu_exact(oy); }
                if (EPI == 2) {
                    float2 rv = *reinterpret_cast<const float2*>(resid + (size_t)r * N + col);
                    ox += rv.x; oy += rv.y;
                    *reinterpret_cast<float2*>((float*)Cout + (size_t)r * N + col) = make_float2(ox, oy);
                } else {
                    *reinterpret_cast<__half2*>((__half*)Cout + (size_t)r * N + col) =
                        __floats2half2_rn(ox, oy);
                }
            }
        }
    }
}

__global__ void __launch_bounds__(256, 2) qkv_kernel(
    const __half* __restrict__ src16, const __half* __restrict__ wt,
    const float* __restrict__ bq, const float* __restrict__ bk, const float* __restrict__ bv,
    __half* __restrict__ q, __half* __restrict__ k, __half* __restrict__ v)
{
    const __half* Bt; const float* b; __half* out;
    if (blockIdx.z == 0)      { Bt = wt + WT_Q; b = bq; out = q; }
    else if (blockIdx.z == 1) { Bt = wt + WT_K; b = bk; out = k; }
    else                      { Bt = wt + WT_V; b = bv; out = v; }
    gemm_body<0>(src16, Bt, b, nullptr, out, DD, DD, blockIdx.x, blockIdx.y);
}

template<int EPI>
__global__ void __launch_bounds__(256, 2) gemm_kernel(
    const __half* __restrict__ A, const __half* __restrict__ Bt,
    const float* __restrict__ bias, const float* __restrict__ resid,
    void* __restrict__ C, int N, int K)
{
    gemm_body<EPI>(A, Bt, bias, resid, C, N, K, blockIdx.x, blockIdx.y);
}

// ---------------- weight transpose fp32[K,N] -> fp16[N,K] ----------------
__global__ void __launch_bounds__(256) transpose4_kernel(
    const float* __restrict__ w0, const float* __restrict__ w1,
    const float* __restrict__ w2, const float* __restrict__ w3,
    __half* __restrict__ out)
{
    __shared__ float t[32][33];
    const float* in = (blockIdx.z == 0) ? w0 : (blockIdx.z == 1) ? w1 : (blockIdx.z == 2) ? w2 : w3;
    __half* o = out + (size_t)blockIdx.z * DD * DD;
    const int tx = threadIdx.x, ty = threadIdx.y;
    const int x0 = blockIdx.x * 32, y0 = blockIdx.y * 32;
    #pragma unroll
    for (int j = 0; j < 4; j++)
        t[ty + 8 * j][tx] = in[(size_t)(y0 + ty + 8 * j) * DD + x0 + tx];
    __syncthreads();
    #pragma unroll
    for (int j = 0; j < 4; j++)
        o[(size_t)(x0 + ty + 8 * j) * DD + y0 + tx] = __float2half(t[tx][ty + 8 * j]);
}

__global__ void __launch_bounds__(256) transpose16_kernel(
    const float* __restrict__ in, __half* __restrict__ out, int K, int N)
{
    __shared__ float t[32][33];
    const int tx = threadIdx.x, ty = threadIdx.y;
    const int x0 = blockIdx.x * 32, y0 = blockIdx.y * 32;
    #pragma unroll
    for (int j = 0; j < 4; j++)
        t[ty + 8 * j][tx] = in[(size_t)(y0 + ty + 8 * j) * N + x0 + tx];
    __syncthreads();
    #pragma unroll
    for (int j = 0; j < 4; j++)
        out[(size_t)(x0 + ty + 8 * j) * K + y0 + tx] = __float2half(t[tx][ty + 8 * j]);
}

// ---------------- fp32 -> fp16 convert ----------------
__global__ void __launch_bounds__(256) cvt16_kernel(
    const float* __restrict__ in, __half* __restrict__ out, int n4)
{
    int i = blockIdx.x * 256 + threadIdx.x;
    if (i < n4) {
        float4 v = reinterpret_cast<const float4*>(in)[i];
        h4 o;
        o.a = __floats2half2_rn(v.x, v.y);
        o.b = __floats2half2_rn(v.z, v.w);
        reinterpret_cast<h4*>(out)[i] = o;
    }
}

// ---------------- fused attention per (b,h) — fp16 mma + half2 exp (unchanged R8) ----------------
#define AT_QS 0
#define AT_KS 13824
#define AT_VT 27648
#define AT_SS 40960
#define AT_PS 0
#define QROWB 144
#define VROWB 208
#define SROWF 100
#define SMEM_ATTN 79360

__global__ void __launch_bounds__(256, 2) attn_kernel(
    const __half* __restrict__ q, const __half* __restrict__ k, const __half* __restrict__ v,
    const float* __restrict__ matrix, float* __restrict__ scores_out, __half* __restrict__ ao)
{
    extern __shared__ char sm[];
    const int bh = blockIdx.x;
    const int b = bh / HH, h = bh % HH;
    const int tid = threadIdx.x;
    const int lane = tid & 31;
    const int wid  = tid >> 5;
    const int wm   = wid >> 2;
    const int wn   = wid & 3;
    const int lq   = lane & 3;
    const int lg   = lane >> 2;
    const size_t base = ((size_t)b * LL) * DD + h * HDIM;

    float* ss = reinterpret_cast<float*>(sm + AT_SS);

    for (int idx = tid; idx < LL * 32; idx += 256) {
        int l = idx >> 5, d2 = idx & 31;
        __half2 qv = *reinterpret_cast<const __half2*>(q + base + (size_t)l * DD + 2 * d2);
        __half2 kv = *reinterpret_cast<const __half2*>(k + base + (size_t)l * DD + 2 * d2);
        __half2 vv = *reinterpret_cast<const __half2*>(v + base + (size_t)l * DD + 2 * d2);
        *reinterpret_cast<__half2*>(sm + AT_QS + l * QROWB + d2 * 4) = qv;
        *reinterpret_cast<__half2*>(sm + AT_KS + l * QROWB + d2 * 4) = kv;
        *reinterpret_cast<__half*>(sm + AT_VT + (2 * d2    ) * VROWB + l * 2) = __low2half(vv);
        *reinterpret_cast<__half*>(sm + AT_VT + (2 * d2 + 1) * VROWB + l * 2) = __high2half(vv);
    }
    __syncthreads();

    const float* mb  = matrix     + (size_t)bh * LL * LL;
    float*       sob = scores_out + (size_t)bh * LL * LL;

    {
        float accS[3][3][4];
        #pragma unroll
        for (int mt = 0; mt < 3; mt++)
            #pragma unroll
            for (int nt = 0; nt < 3; nt++)
                #pragma unroll
                for (int r = 0; r < 4; r++) accS[mt][nt][r] = 0.f;

        #pragma unroll
        for (int q0 = 0; q0 < HDIM; q0 += 16) {
            const int kb = 2 * (q0 + 2 * lq);
            uint32_t af[3][4], bf[3][2];
            #pragma unroll
            for (int mt = 0; mt < 3; mt++) {
                const char* p = sm + AT_QS + (wm * 48 + mt * 16 + lg) * QROWB + kb;
                af[mt][0] = *reinterpret_cast<const uint32_t*>(p);
                af[mt][1] = *reinterpret_cast<const uint32_t*>(p + 8 * QROWB);
                af[mt][2] = *reinterpret_cast<const uint32_t*>(p + 16);
                af[mt][3] = *reinterpret_cast<const uint32_t*>(p + 8 * QROWB + 16);
            }
            #pragma unroll
            for (int nt = 0; nt < 3; nt++) {
                const char* p = sm + AT_KS + (wn * 24 + nt * 8 + lg) * QROWB + kb;
                bf[nt][0] = *reinterpret_cast<const uint32_t*>(p);
                bf[nt][1] = *reinterpret_cast<const uint32_t*>(p + 16);
            }
            #pragma unroll
            for (int mt = 0; mt < 3; mt++)
                #pragma unroll
                for (int nt = 0; nt < 3; nt++)
                    mma_f16(accS[mt][nt], af[mt], bf[nt]);
        }

        #pragma unroll
        for (int mt = 0; mt < 3; mt++) {
            #pragma unroll
            for (int nt = 0; nt < 3; nt++) {
                int row = wm * 48 + mt * 16 + lg;
                int col = wn * 24 + nt * 8 + 2 * lq;
                #pragma unroll
                for (int half_i = 0; half_i < 2; half_i++) {
                    int r = row + half_i * 8;
                    float2 mv = *reinterpret_cast<const float2*>(mb + (size_t)r * LL + col);
                    float sx = accS[mt][nt][half_i * 2 + 0] * mv.x * SCALE;
                    float sy = accS[mt][nt][half_i * 2 + 1] * mv.y * SCALE;
                    *reinterpret_cast<float2*>(sob + (size_t)r * LL + col) = make_float2(sx, sy);
                    ss[r * SROWF + col]     = sx;
                    ss[r * SROWF + col + 1] = sy;
                }
            }
        }
    }
    __syncthreads();

    {
        #pragma unroll
        for (int rr = 0; rr < 6; rr++) {
            const int ra = wid + rr * 16;
            const int rb = ra + 8;
            float a0 = ss[ra * SROWF + lane];
            float a1 = ss[ra * SROWF + lane + 32];
            float a2 = ss[ra * SROWF + lane + 64];
            float b0 = ss[rb * SROWF + lane];
            float b1 = ss[rb * SROWF + lane + 32];
            float b2 = ss[rb * SROWF + lane + 64];
            float ma = fmaxf(fmaxf(a0, a1), a2);
            float mbv = fmaxf(fmaxf(b0, b1), b2);
            #pragma unroll
            for (int o = 16; o > 0; o >>= 1) {
                ma  = fmaxf(ma,  __shfl_xor_sync(0xffffffffu, ma,  o));
                mbv = fmaxf(mbv, __shfl_xor_sync(0xffffffffu, mbv, o));
            }
            __half2 e01 = __floats2half2_rn((a0 - ma) * LOG2E, (a1 - ma) * LOG2E);
            __half2 e2b0 = __floats2half2_rn((a2 - ma) * LOG2E, (b0 - mbv) * LOG2E);
            __half2 e12 = __floats2half2_rn((b1 - mbv) * LOG2E, (b2 - mbv) * LOG2E);
            uint32_t p01  = h2ex2(*reinterpret_cast<uint32_t*>(&e01));
            uint32_t p2b0 = h2ex2(*reinterpret_cast<uint32_t*>(&e2b0));
            uint32_t p12  = h2ex2(*reinterpret_cast<uint32_t*>(&e12));
            float2 f01  = __half22float2(*reinterpret_cast<__half2*>(&p01));
            float2 f2b0 = __half22float2(*reinterpret_cast<__half2*>(&p2b0));
            float2 f12  = __half22float2(*reinterpret_cast<__half2*>(&p12));
            float sa = f01.x + f01.y + f2b0.x;
            float sb = f2b0.y + f12.x + f12.y;
            #pragma unroll
            for (int o = 16; o > 0; o >>= 1) {
                sa += __shfl_xor_sync(0xffffffffu, sa, o);
                sb += __shfl_xor_sync(0xffffffffu, sb, o);
            }
            float inva = 1.f / sa, invb = 1.f / sb;
            __half2 ia2 = __floats2half2_rn(inva, inva);
            __half2 iab = __floats2half2_rn(inva, invb);
            __half2 ib2 = __floats2half2_rn(invb, invb);
            __half2 o01  = __hmul2(*reinterpret_cast<__half2*>(&p01),  ia2);
            __half2 o2b0 = __hmul2(*reinterpret_cast<__half2*>(&p2b0), iab);
            __half2 o12  = __hmul2(*reinterpret_cast<__half2*>(&p12),  ib2);
            *reinterpret_cast<__half*>(sm + AT_PS + ra * VROWB + (lane     ) * 2) = __low2half(o01);
            *reinterpret_cast<__half*>(sm + AT_PS + ra * VROWB + (lane + 32) * 2) = __high2half(o01);
            *reinterpret_cast<__half*>(sm + AT_PS + ra * VROWB + (lane + 64) * 2) = __low2half(o2b0);
            *reinterpret_cast<__half*>(sm + AT_PS + rb * VROWB + (lane     ) * 2) = __high2half(o2b0);
            *reinterpret_cast<__half*>(sm + AT_PS + rb * VROWB + (lane + 32) * 2) = __low2half(o12);
            *reinterpret_cast<__half*>(sm + AT_PS + rb * VROWB + (lane + 64) * 2) = __high2half(o12);
        }
    }
    __syncthreads();

    {
        float accO[3][2][4];
        #pragma unroll
        for (int mt = 0; mt < 3; mt++)
            #pragma unroll
            for (int nt = 0; nt < 2; nt++)
                #pragma unroll
                for (int r = 0; r < 4; r++) accO[mt][nt][r] = 0.f;

        #pragma unroll
        for (int k0 = 0; k0 < LL; k0 += 16) {
            const int kb = 2 * (k0 + 2 * lq);
            uint32_t af[3][4], bf[2][2];
            #pragma unroll
            for (int mt = 0; mt < 3; mt++) {
                const char* p = sm + AT_PS + (wm * 48 + mt * 16 + lg) * VROWB + kb;
                af[mt][0] = *reinterpret_cast<const uint32_t*>(p);
                af[mt][1] = *reinterpret_cast<const uint32_t*>(p + 8 * VROWB);
                af[mt][2] = *reinterpret_cast<const uint32_t*>(p + 16);
                af[mt][3] = *reinterpret_cast<const uint32_t*>(p + 8 * VROWB + 16);
            }
            #pragma unroll
            for (int nt = 0; nt < 2; nt++) {
                const char* p = sm + AT_VT + (wn * 16 + nt * 8 + lg) * VROWB + kb;
                bf[nt][0] = *reinterpret_cast<const uint32_t*>(p);
                bf[nt][1] = *reinterpret_cast<const uint32_t*>(p + 16);
            }
            #pragma unroll
            for (int mt = 0; mt < 3; mt++)
                #pragma unroll
                for (int nt = 0; nt < 2; nt++)
                    mma_f16(accO[mt][nt], af[mt], bf[nt]);
        }

        #pragma unroll
        for (int mt = 0; mt < 3; mt++) {
            #pragma unroll
            for (int nt = 0; nt < 2; nt++) {
                int row = wm * 48 + mt * 16 + lg;
                int col = wn * 16 + nt * 8 + 2 * lq;
                *reinterpret_cast<__half2*>(ao + base + (size_t)row * DD + col) =
                    __floats2half2_rn(accO[mt][nt][0], accO[mt][nt][1]);
                *reinterpret_cast<__half2*>(ao + base + (size_t)(row + 8) * DD + col) =
                    __floats2half2_rn(accO[mt][nt][2], accO[mt][nt][3]);
            }
        }
    }
}

// ---------------- LayerNorm over D=512, warp per row (optional fp16 dual-out) ----------------
__global__ void __launch_bounds__(256) ln_kernel(
    const float* __restrict__ x, const float* __restrict__ gw, const float* __restrict__ bw,
    float* __restrict__ out, __half* __restrict__ out16)
{
    const int row  = blockIdx.x * 8 + (threadIdx.x >> 5);
    const int lane = threadIdx.x & 31;
    const float* xr = x + (size_t)row * DD;
    float4 v[4];
    float s = 0.f, s2 = 0.f;
    #pragma unroll
    for (int t = 0; t < 4; t++) {
        v[t] = *reinterpret_cast<const float4*>(xr + (size_t)(t * 32 + lane) * 4);
        s  += v[t].x + v[t].y + v[t].z + v[t].w;
        s2 += v[t].x * v[t].x + v[t].y * v[t].y + v[t].z * v[t].z + v[t].w * v[t].w;
    }
    #pragma unroll
    for (int o = 16; o > 0; o >>= 1) {
        s  += __shfl_xor_sync(0xffffffffu, s,  o);
        s2 += __shfl_xor_sync(0xffffffffu, s2, o);
    }
    const float mean = s * (1.f / DD);
    const float var  = s2 * (1.f / DD) - mean * mean;
    const float rstd = rsqrtf(var + EPS_LN);
    float* orow = out + (size_t)row * DD;
    #pragma unroll
    for (int t = 0; t < 4; t++) {
        int c = (t * 32 + lane) * 4;
        float4 gv = *reinterpret_cast<const float4*>(gw + c);
        float4 bv = *reinterpret_cast<const float4*>(bw + c);
        float4 r;
        r.x = (v[t].x - mean) * rstd * gv.x + bv.x;
        r.y = (v[t].y - mean) * rstd * gv.y + bv.y;
        r.z = (v[t].z - mean) * rstd * gv.z + bv.z;
        r.w = (v[t].w - mean) * rstd * gv.w + bv.w;
        *reinterpret_cast<float4*>(orow + c) = r;
        if (out16) {
            h4 o;
            o.a = __floats2half2_rn(r.x, r.y);
            o.b = __floats2half2_rn(r.z, r.w);
            *reinterpret_cast<h4*>(out16 + (size_t)row * DD + c) = o;
        }
    }
}

// ---------------- launch ----------------
extern "C" void kernel_launch(void* const* d_in, const int* in_sizes, int n_in,
                              void* d_out, int out_size)
{
    const float* src  = (const float*)d_in[0];
    const float* Wq   = (const float*)d_in[1];  const float* bq  = (const float*)d_in[2];
    const float* Wk   = (const float*)d_in[3];  const float* bk  = (const float*)d_in[4];
    const float* Wv   = (const float*)d_in[5];  const float* bv  = (const float*)d_in[6];
    const float* mat  = (const float*)d_in[7];
    const float* Wo   = (const float*)d_in[8];  const float* bo  = (const float*)d_in[9];
    const float* ln1g = (const float*)d_in[10]; const float* ln1b = (const float*)d_in[11];
    const float* W1   = (const float*)d_in[12]; const float* b1  = (const float*)d_in[13];
    const float* W2   = (const float*)d_in[14]; const float* b2  = (const float*)d_in[15];
    const float* ln2g = (const float*)d_in[16]; const float* ln2b = (const float*)d_in[17];

    float* y_out = (float*)d_out;
    float* scores_out = y_out + (size_t)NT * DD;

    __half *src16, *q16, *k16, *v16, *ao16, *x16, *ff16, *wt;
    float *t, *x;
    cudaGetSymbolAddress((void**)&src16, g_src16);
    cudaGetSymbolAddress((void**)&q16,  g_q16);
    cudaGetSymbolAddress((void**)&k16,  g_k16);
    cudaGetSymbolAddress((void**)&v16,  g_v16);
    cudaGetSymbolAddress((void**)&ao16, g_ao16);
    cudaGetSymbolAddress((void**)&x16,  g_x16);
    cudaGetSymbolAddress((void**)&ff16, g_ff16);
    cudaGetSymbolAddress((void**)&wt,   g_wt16);
    cudaGetSymbolAddress((void**)&t,    g_t);
    cudaGetSymbolAddress((void**)&x,    g_x);

    cudaFuncSetAttribute(qkv_kernel,     cudaFuncAttributeMaxDynamicSharedMemorySize, SMEM_GEMM);
    cudaFuncSetAttribute(gemm_kernel<1>, cudaFuncAttributeMaxDynamicSharedMemorySize, SMEM_GEMM);
    cudaFuncSetAttribute(gemm_kernel<2>, cudaFuncAttributeMaxDynamicSharedMemorySize, SMEM_GEMM);
    cudaFuncSetAttribute(attn_kernel,    cudaFuncAttributeMaxDynamicSharedMemorySize, SMEM_ATTN);

    // ---- prep: src->fp16, weights transpose+fp16 ----
    cvt16_kernel<<<(NT*DD/4 + 255)/256, 256>>>(src, src16, NT*DD/4);
    dim3 tb(32, 8);
    transpose4_kernel<<<dim3(DD/32, DD/32, 4), tb>>>(Wq, Wk, Wv, Wo, wt);
    transpose16_kernel<<<dim3(DFF/32, DD/32), tb>>>(W1, wt + WT_1, DD, DFF);
    transpose16_kernel<<<dim3(DD/32, DFF/32), tb>>>(W2, wt + WT_2, DFF, DD);

    dim3 gqkv(DD / 128, NT / 128, 3);   // (4, 192, 3)
    dim3 g512(DD / 128, NT / 128);      // (4, 192)
    dim3 gff (DFF / 128, NT / 128);     // (16, 192)

    qkv_kernel<<<gqkv, 256, SMEM_GEMM>>>(src16, wt, bq, bk, bv, q16, k16, v16);
    attn_kernel<<<BB * HH, 256, SMEM_ATTN>>>(q16, k16, v16, mat, scores_out, ao16);
    gemm_kernel<2><<<g512, 256, SMEM_GEMM>>>(ao16, wt + WT_O, bo, src, t, DD, DD);
    ln_kernel<<<NT / 8, 256>>>(t, ln1g, ln1b, x, x16);
    gemm_kernel<1><<<gff, 256, SMEM_GEMM>>>(x16, wt + WT_1, b1, nullptr, ff16, DFF, DD);
    gemm_kernel<2><<<g512, 256, SMEM_GEMM>>>(ff16, wt + WT_2, b2, x, t, DD, DFF);
    ln_kernel<<<NT / 8, 256>>>(t, ln2g, ln2b, y_out, nullptr);
}

// round 17
// speedup vs baseline: 1.0911x; 1.0911x over previous
#include <cuda_runtime.h>
#include <cuda_fp16.h>
#include <math.h>
#include <stdint.h>

// ---------------- problem dims ----------------
#define BB 256
#define LL 96
#define DD 512
#define HH 8
#define HDIM 64
#define DFF 2048
#define NT (BB*LL)          // 24576 tokens
#define SCALE 0.125f
#define EPS_LN 1e-5f
#define LOG2E 1.4426950408889634f

// ---------------- scratch (no allocs allowed) ----------------
__device__ __align__(16) __half g_src16[NT*DD];
__device__ __align__(16) __half g_q16 [NT*DD];
__device__ __align__(16) __half g_k16 [NT*DD];
__device__ __align__(16) __half g_v16 [NT*DD];
__device__ __align__(16) __half g_ao16[NT*DD];
__device__ __align__(16) __half g_x16 [NT*DD];
__device__ __align__(16) __half g_ff16[NT*DFF];
__device__ float g_t [NT*DD];
__device__ float g_x [NT*DD];
__device__ __align__(16) __half g_wt16[4*DD*DD + 2*DD*DFF];   // transposed fp16 weights

// offsets into g_wt16 (halves)
#define WT_Q  0
#define WT_K  (DD*DD)
#define WT_V  (2*DD*DD)
#define WT_O  (3*DD*DD)
#define WT_1  (4*DD*DD)            // W1T [2048,512]
#define WT_2  (4*DD*DD + DD*DFF)   // W2T [512,2048]

struct h4 { __half2 a, b; };

// ---------------- helpers ----------------
__device__ __forceinline__ void cp_async16(uint32_t dst, const void* src) {
    asm volatile("cp.async.cg.shared.global [%0], [%1], 16;" :: "r"(dst), "l"(src));
}
__device__ __forceinline__ void cp_commit() { asm volatile("cp.async.commit_group;" ::: "memory"); }
__device__ __forceinline__ void cp_wait1()  { asm volatile("cp.async.wait_group 1;" ::: "memory"); }

__device__ __forceinline__ void mma_f16(float* c, const uint32_t* a, const uint32_t* b) {
    asm volatile(
        "mma.sync.aligned.m16n8k16.row.col.f32.f16.f16.f32 "
        "{%0,%1,%2,%3}, {%4,%5,%6,%7}, {%8,%9}, {%0,%1,%2,%3};\n"
        : "+f"(c[0]), "+f"(c[1]), "+f"(c[2]), "+f"(c[3])
        : "r"(a[0]), "r"(a[1]), "r"(a[2]), "r"(a[3]), "r"(b[0]), "r"(b[1]));
}

__device__ __forceinline__ void ldsm_x4(uint32_t* r, uint32_t addr) {
    asm volatile("ldmatrix.sync.aligned.m8n8.x4.shared.b16 {%0,%1,%2,%3}, [%4];"
        : "=r"(r[0]), "=r"(r[1]), "=r"(r[2]), "=r"(r[3]) : "r"(addr));
}
__device__ __forceinline__ void ldsm_x2(uint32_t* r, uint32_t addr) {
    asm volatile("ldmatrix.sync.aligned.m8n8.x2.shared.b16 {%0,%1}, [%2];"
        : "=r"(r[0]), "=r"(r[1]) : "r"(addr));
}

__device__ __forceinline__ uint32_t h2ex2(uint32_t x) {
    uint32_t r;
    asm("ex2.approx.f16x2 %0, %1;" : "=r"(r) : "r"(x));
    return r;
}

__device__ __forceinline__ float gelu_exact(float x) {
    return 0.5f * x * (1.f + erff(x * 0.70710678118654752f));
}

// ---------------- fp16 MMA GEMM: 128x128 tile, BK=64, 3-stage cp.async + ldmatrix ----------------
#define STAGES 3
#define ROWB 144                       // 64 halves (128 B) + 16 B pad
#define A_ST (128*ROWB)                // 18432
#define B_ST (128*ROWB)
#define SMEM_GEMM (STAGES*(A_ST+B_ST)) // 110592 B

// EPI: 0 = bias -> fp16 out; 1 = bias+gelu -> fp16 out; 2 = bias+residual -> fp32 out
template<int EPI>
__device__ __forceinline__ void gemm_body(
    const __half* __restrict__ A, const __half* __restrict__ Bt,
    const float* __restrict__ bias, const float* __restrict__ resid,
    void* __restrict__ Cout, int N, int K, int bx, int by)
{
    extern __shared__ char smem[];
    const uint32_t smemA = (uint32_t)__cvta_generic_to_shared(smem);
    const uint32_t smemB = smemA + STAGES * A_ST;

    const int tid  = threadIdx.x;
    const int lane = tid & 31;
    const int wid  = tid >> 5;
    const int wm   = wid >> 2;
    const int wn   = wid & 3;
    const int lq   = lane & 3;
    const int lg   = lane >> 2;

    const int a_row  = (lane & 7) | (((lane >> 3) & 1) << 3);
    const int a_c16  = (lane >> 4) << 4;
    const int b_row  = lane & 7;
    const int b_c16  = ((lane >> 3) & 1) << 4;

    const __half* Ablk = A  + (size_t)by * 128 * K;
    const __half* Bblk = Bt + (size_t)bx * 128 * K;

    float acc[4][4][4];
    #pragma unroll
    for (int mt = 0; mt < 4; mt++)
        #pragma unroll
        for (int nt = 0; nt < 4; nt++)
            #pragma unroll
            for (int r = 0; r < 4; r++) acc[mt][nt][r] = 0.f;

    const int KT = K >> 6;    // K/64

    auto load_tile = [&](int kt) {
        const int s = kt % STAGES;
        const int kof = kt << 6;   // halves
        #pragma unroll
        for (int i = 0; i < 4; i++) {
            int c = tid + (i << 8);
            int r = c >> 3, cc = c & 7;
            cp_async16(smemA + s*A_ST + r*ROWB + cc*16, Ablk + (size_t)r * K + kof + cc*8);
            cp_async16(smemB + s*B_ST + r*ROWB + cc*16, Bblk + (size_t)r * K + kof + cc*8);
        }
    };

    // prologue: tiles 0,1
    load_tile(0); cp_commit();
    if (KT > 1) { load_tile(1); }
    cp_commit();

    const uint32_t a_lane_base = smemA + (wm * 64 + a_row) * ROWB + a_c16;
    const uint32_t b_lane_base = smemB + (wn * 32 + b_row) * ROWB + b_c16;

    for (int kt = 0; kt < KT; kt++) {
        cp_wait1();          // tile kt resident (<=1 group pending: kt+1)
        __syncthreads();

        const int s = kt % STAGES;
        const uint32_t abase = a_lane_base + s * A_ST;
        const uint32_t bbase = b_lane_base + s * B_ST;

        // q0 = 0 fragment loads FIRST: overlap LDSM latency with the cp.async issue burst below
        uint32_t af[4][4], bf[4][2];
        #pragma unroll
        for (int mt = 0; mt < 4; mt++)
            ldsm_x4(af[mt], abase + mt * 16 * ROWB);
        #pragma unroll
        for (int nt = 0; nt < 4; nt++)
            ldsm_x2(bf[nt], bbase + nt * 8 * ROWB);

        int nk = kt + 2;
        if (nk < KT) load_tile(nk);
        cp_commit();

        // mma for q0 = 0
        #pragma unroll
        for (int mt = 0; mt < 4; mt++)
            #pragma unroll
            for (int nt = 0; nt < 4; nt++)
                mma_f16(acc[mt][nt], af[mt], bf[nt]);

        // q0 = 16, 32, 48
        #pragma unroll
        for (int q0 = 16; q0 < 64; q0 += 16) {
            const int kb = 2 * q0;
            #pragma unroll
            for (int mt = 0; mt < 4; mt++)
                ldsm_x4(af[mt], abase + mt * 16 * ROWB + kb);
            #pragma unroll
            for (int nt = 0; nt < 4; nt++)
                ldsm_x2(bf[nt], bbase + nt * 8 * ROWB + kb);
            #pragma unroll
            for (int mt = 0; mt < 4; mt++)
                #pragma unroll
                for (int nt = 0; nt < 4; nt++)
                    mma_f16(acc[mt][nt], af[mt], bf[nt]);
        }
    }

    #pragma unroll
    for (int mt = 0; mt < 4; mt++) {
        #pragma unroll
        for (int nt = 0; nt < 4; nt++) {
            int row = by * 128 + wm * 64 + mt * 16 + lg;
            int col = bx * 128 + wn * 32 + nt * 8 + 2 * lq;
            float2 bv = *reinterpret_cast<const float2*>(bias + col);
            #pragma unroll
            for (int half_i = 0; half_i < 2; half_i++) {
                int r = row + half_i * 8;
                float ox = acc[mt][nt][half_i * 2 + 0] + bv.x;
                float oy = acc[mt][nt][half_i * 2 + 1] + bv.y;
                if (EPI == 1) { ox = gelu_exact(ox); oy = gelu_exact(oy); }
                if (EPI == 2) {
                    float2 rv = *reinterpret_cast<const float2*>(resid + (size_t)r * N + col);
                    ox += rv.x; oy += rv.y;
                    *reinterpret_cast<float2*>((float*)Cout + (size_t)r * N + col) = make_float2(ox, oy);
                } else {
                    *reinterpret_cast<__half2*>((__half*)Cout + (size_t)r * N + col) =
                        __floats2half2_rn(ox, oy);
                }
            }
        }
    }
}

__global__ void __launch_bounds__(256, 2) qkv_kernel(
    const __half* __restrict__ src16, const __half* __restrict__ wt,
    const float* __restrict__ bq, const float* __restrict__ bk, const float* __restrict__ bv,
    __half* __restrict__ q, __half* __restrict__ k, __half* __restrict__ v)
{
    const __half* Bt; const float* b; __half* out;
    if (blockIdx.z == 0)      { Bt = wt + WT_Q; b = bq; out = q; }
    else if (blockIdx.z == 1) { Bt = wt + WT_K; b = bk; out = k; }
    else                      { Bt = wt + WT_V; b = bv; out = v; }
    gemm_body<0>(src16, Bt, b, nullptr, out, DD, DD, blockIdx.x, blockIdx.y);
}

template<int EPI>
__global__ void __launch_bounds__(256, 2) gemm_kernel(
    const __half* __restrict__ A, const __half* __restrict__ Bt,
    const float* __restrict__ bias, const float* __restrict__ resid,
    void* __restrict__ C, int N, int K)
{
    gemm_body<EPI>(A, Bt, bias, resid, C, N, K, blockIdx.x, blockIdx.y);
}

// ---------------- weight transpose fp32[K,N] -> fp16[N,K] ----------------
__global__ void __launch_bounds__(256) transpose4_kernel(
    const float* __restrict__ w0, const float* __restrict__ w1,
    const float* __restrict__ w2, const float* __restrict__ w3,
    __half* __restrict__ out)
{
    __shared__ float t[32][33];
    const float* in = (blockIdx.z == 0) ? w0 : (blockIdx.z == 1) ? w1 : (blockIdx.z == 2) ? w2 : w3;
    __half* o = out + (size_t)blockIdx.z * DD * DD;
    const int tx = threadIdx.x, ty = threadIdx.y;
    const int x0 = blockIdx.x * 32, y0 = blockIdx.y * 32;
    #pragma unroll
    for (int j = 0; j < 4; j++)
        t[ty + 8 * j][tx] = in[(size_t)(y0 + ty + 8 * j) * DD + x0 + tx];
    __syncthreads();
    #pragma unroll
    for (int j = 0; j < 4; j++)
        o[(size_t)(x0 + ty + 8 * j) * DD + y0 + tx] = __float2half(t[tx][ty + 8 * j]);
}

__global__ void __launch_bounds__(256) transpose16_kernel(
    const float* __restrict__ in, __half* __restrict__ out, int K, int N)
{
    __shared__ float t[32][33];
    const int tx = threadIdx.x, ty = threadIdx.y;
    const int x0 = blockIdx.x * 32, y0 = blockIdx.y * 32;
    #pragma unroll
    for (int j = 0; j < 4; j++)
        t[ty + 8 * j][tx] = in[(size_t)(y0 + ty + 8 * j) * N + x0 + tx];
    __syncthreads();
    #pragma unroll
    for (int j = 0; j < 4; j++)
        out[(size_t)(x0 + ty + 8 * j) * K + y0 + tx] = __float2half(t[tx][ty + 8 * j]);
}

// ---------------- fp32 -> fp16 convert ----------------
__global__ void __launch_bounds__(256) cvt16_kernel(
    const float* __restrict__ in, __half* __restrict__ out, int n4)
{
    int i = blockIdx.x * 256 + threadIdx.x;
    if (i < n4) {
        float4 v = reinterpret_cast<const float4*>(in)[i];
        h4 o;
        o.a = __floats2half2_rn(v.x, v.y);
        o.b = __floats2half2_rn(v.z, v.w);
        reinterpret_cast<h4*>(out)[i] = o;
    }
}

// ---------------- fused attention per (b,h) — fp16 mma + half2 exp ----------------
#define AT_QS 0
#define AT_KS 13824
#define AT_VT 27648
#define AT_SS 40960
#define AT_PS 0
#define QROWB 144
#define VROWB 208
#define SROWF 100
#define SMEM_ATTN 79360

__global__ void __launch_bounds__(256, 2) attn_kernel(
    const __half* __restrict__ q, const __half* __restrict__ k, const __half* __restrict__ v,
    const float* __restrict__ matrix, float* __restrict__ scores_out, __half* __restrict__ ao)
{
    extern __shared__ char sm[];
    const int bh = blockIdx.x;
    const int b = bh / HH, h = bh % HH;
    const int tid = threadIdx.x;
    const int lane = tid & 31;
    const int wid  = tid >> 5;
    const int wm   = wid >> 2;
    const int wn   = wid & 3;
    const int lq   = lane & 3;
    const int lg   = lane >> 2;
    const size_t base = ((size_t)b * LL) * DD + h * HDIM;

    float* ss = reinterpret_cast<float*>(sm + AT_SS);

    for (int idx = tid; idx < LL * 32; idx += 256) {
        int l = idx >> 5, d2 = idx & 31;
        __half2 qv = *reinterpret_cast<const __half2*>(q + base + (size_t)l * DD + 2 * d2);
        __half2 kv = *reinterpret_cast<const __half2*>(k + base + (size_t)l * DD + 2 * d2);
        __half2 vv = *reinterpret_cast<const __half2*>(v + base + (size_t)l * DD + 2 * d2);
        *reinterpret_cast<__half2*>(sm + AT_QS + l * QROWB + d2 * 4) = qv;
        *reinterpret_cast<__half2*>(sm + AT_KS + l * QROWB + d2 * 4) = kv;
        *reinterpret_cast<__half*>(sm + AT_VT + (2 * d2    ) * VROWB + l * 2) = __low2half(vv);
        *reinterpret_cast<__half*>(sm + AT_VT + (2 * d2 + 1) * VROWB + l * 2) = __high2half(vv);
    }
    __syncthreads();

    const float* mb  = matrix     + (size_t)bh * LL * LL;
    float*       sob = scores_out + (size_t)bh * LL * LL;

    {
        float accS[3][3][4];
        #pragma unroll
        for (int mt = 0; mt < 3; mt++)
            #pragma unroll
            for (int nt = 0; nt < 3; nt++)
                #pragma unroll
                for (int r = 0; r < 4; r++) accS[mt][nt][r] = 0.f;

        #pragma unroll
        for (int q0 = 0; q0 < HDIM; q0 += 16) {
            const int kb = 2 * (q0 + 2 * lq);
            uint32_t af[3][4], bf[3][2];
            #pragma unroll
            for (int mt = 0; mt < 3; mt++) {
                const char* p = sm + AT_QS + (wm * 48 + mt * 16 + lg) * QROWB + kb;
                af[mt][0] = *reinterpret_cast<const uint32_t*>(p);
                af[mt][1] = *reinterpret_cast<const uint32_t*>(p + 8 * QROWB);
                af[mt][2] = *reinterpret_cast<const uint32_t*>(p + 16);
                af[mt][3] = *reinterpret_cast<const uint32_t*>(p + 8 * QROWB + 16);
            }
            #pragma unroll
            for (int nt = 0; nt < 3; nt++) {
                const char* p = sm + AT_KS + (wn * 24 + nt * 8 + lg) * QROWB + kb;
                bf[nt][0] = *reinterpret_cast<const uint32_t*>(p);
                bf[nt][1] = *reinterpret_cast<const uint32_t*>(p + 16);
            }
            #pragma unroll
            for (int mt = 0; mt < 3; mt++)
                #pragma unroll
                for (int nt = 0; nt < 3; nt++)
                    mma_f16(accS[mt][nt], af[mt], bf[nt]);
        }

        #pragma unroll
        for (int mt = 0; mt < 3; mt++) {
            #pragma unroll
            for (int nt = 0; nt < 3; nt++) {
                int row = wm * 48 + mt * 16 + lg;
                int col = wn * 24 + nt * 8 + 2 * lq;
                #pragma unroll
                for (int half_i = 0; half_i < 2; half_i++) {
                    int r = row + half_i * 8;
                    float2 mv = *reinterpret_cast<const float2*>(mb + (size_t)r * LL + col);
                    float sx = accS[mt][nt][half_i * 2 + 0] * mv.x * SCALE;
                    float sy = accS[mt][nt][half_i * 2 + 1] * mv.y * SCALE;
                    __stcs(reinterpret_cast<float2*>(sob + (size_t)r * LL + col), make_float2(sx, sy));
                    ss[r * SROWF + col]     = sx;
                    ss[r * SROWF + col + 1] = sy;
                }
            }
        }
    }
    __syncthreads();

    {
        #pragma unroll
        for (int rr = 0; rr < 6; rr++) {
            const int ra = wid + rr * 16;
            const int rb = ra + 8;
            float a0 = ss[ra * SROWF + lane];
            float a1 = ss[ra * SROWF + lane + 32];
            float a2 = ss[ra * SROWF + lane + 64];
            float b0 = ss[rb * SROWF + lane];
            float b1 = ss[rb * SROWF + lane + 32];
            float b2 = ss[rb * SROWF + lane + 64];
            float ma = fmaxf(fmaxf(a0, a1), a2);
            float mbv = fmaxf(fmaxf(b0, b1), b2);
            #pragma unroll
            for (int o = 16; o > 0; o >>= 1) {
                ma  = fmaxf(ma,  __shfl_xor_sync(0xffffffffu, ma,  o));
                mbv = fmaxf(mbv, __shfl_xor_sync(0xffffffffu, mbv, o));
            }
            __half2 e01 = __floats2half2_rn((a0 - ma) * LOG2E, (a1 - ma) * LOG2E);
            __half2 e2b0 = __floats2half2_rn((a2 - ma) * LOG2E, (b0 - mbv) * LOG2E);
            __half2 e12 = __floats2half2_rn((b1 - mbv) * LOG2E, (b2 - mbv) * LOG2E);
            uint32_t p01  = h2ex2(*reinterpret_cast<uint32_t*>(&e01));
            uint32_t p2b0 = h2ex2(*reinterpret_cast<uint32_t*>(&e2b0));
            uint32_t p12  = h2ex2(*reinterpret_cast<uint32_t*>(&e12));
            float2 f01  = __half22float2(*reinterpret_cast<__half2*>(&p01));
            float2 f2b0 = __half22float2(*reinterpret_cast<__half2*>(&p2b0));
            float2 f12  = __half22float2(*reinterpret_cast<__half2*>(&p12));
            float sa = f01.x + f01.y + f2b0.x;
            float sb = f2b0.y + f12.x + f12.y;
            #pragma unroll
            for (int o = 16; o > 0; o >>= 1) {
                sa += __shfl_xor_sync(0xffffffffu, sa, o);
                sb += __shfl_xor_sync(0xffffffffu, sb, o);
            }
            float inva = 1.f / sa, invb = 1.f / sb;
            __half2 ia2 = __floats2half2_rn(inva, inva);
            __half2 iab = __floats2half2_rn(inva, invb);
            __half2 ib2 = __floats2half2_rn(invb, invb);
            __half2 o01  = __hmul2(*reinterpret_cast<__half2*>(&p01),  ia2);
            __half2 o2b0 = __hmul2(*reinterpret_cast<__half2*>(&p2b0), iab);
            __half2 o12  = __hmul2(*reinterpret_cast<__half2*>(&p12),  ib2);
            *reinterpret_cast<__half*>(sm + AT_PS + ra * VROWB + (lane     ) * 2) = __low2half(o01);
            *reinterpret_cast<__half*>(sm + AT_PS + ra * VROWB + (lane + 32) * 2) = __high2half(o01);
            *reinterpret_cast<__half*>(sm + AT_PS + ra * VROWB + (lane + 64) * 2) = __low2half(o2b0);
            *reinterpret_cast<__half*>(sm + AT_PS + rb * VROWB + (lane     ) * 2) = __high2half(o2b0);
            *reinterpret_cast<__half*>(sm + AT_PS + rb * VROWB + (lane + 32) * 2) = __low2half(o12);
            *reinterpret_cast<__half*>(sm + AT_PS + rb * VROWB + (lane + 64) * 2) = __high2half(o12);
        }
    }
    __syncthreads();

    {
        float accO[3][2][4];
        #pragma unroll
        for (int mt = 0; mt < 3; mt++)
            #pragma unroll
            for (int nt = 0; nt < 2; nt++)
                #pragma unroll
                for (int r = 0; r < 4; r++) accO[mt][nt][r] = 0.f;

        #pragma unroll
        for (int k0 = 0; k0 < LL; k0 += 16) {
            const int kb = 2 * (k0 + 2 * lq);
            uint32_t af[3][4], bf[2][2];
            #pragma unroll
            for (int mt = 0; mt < 3; mt++) {
                const char* p = sm + AT_PS + (wm * 48 + mt * 16 + lg) * VROWB + kb;
                af[mt][0] = *reinterpret_cast<const uint32_t*>(p);
                af[mt][1] = *reinterpret_cast<const uint32_t*>(p + 8 * VROWB);
                af[mt][2] = *reinterpret_cast<const uint32_t*>(p + 16);
                af[mt][3] = *reinterpret_cast<const uint32_t*>(p + 8 * VROWB + 16);
            }
            #pragma unroll
            for (int nt = 0; nt < 2; nt++) {
                const char* p = sm + AT_VT + (wn * 16 + nt * 8 + lg) * VROWB + kb;
                bf[nt][0] = *reinterpret_cast<const uint32_t*>(p);
                bf[nt][1] = *reinterpret_cast<const uint32_t*>(p + 16);
            }
            #pragma unroll
            for (int mt = 0; mt < 3; mt++)
                #pragma unroll
                for (int nt = 0; nt < 2; nt++)
                    mma_f16(accO[mt][nt], af[mt], bf[nt]);
        }

        #pragma unroll
        for (int mt = 0; mt < 3; mt++) {
            #pragma unroll
            for (int nt = 0; nt < 2; nt++) {
                int row = wm * 48 + mt * 16 + lg;
                int col = wn * 16 + nt * 8 + 2 * lq;
                *reinterpret_cast<__half2*>(ao + base + (size_t)row * DD + col) =
                    __floats2half2_rn(accO[mt][nt][0], accO[mt][nt][1]);
                *reinterpret_cast<__half2*>(ao + base + (size_t)(row + 8) * DD + col) =
                    __floats2half2_rn(accO[mt][nt][2], accO[mt][nt][3]);
            }
        }
    }
}

// ---------------- LayerNorm over D=512, warp per row (optional fp16 dual-out) ----------------
__global__ void __launch_bounds__(256) ln_kernel(
    const float* __restrict__ x, const float* __restrict__ gw, const float* __restrict__ bw,
    float* __restrict__ out, __half* __restrict__ out16)
{
    const int row  = blockIdx.x * 8 + (threadIdx.x >> 5);
    const int lane = threadIdx.x & 31;
    const float* xr = x + (size_t)row * DD;
    float4 v[4];
    float s = 0.f, s2 = 0.f;
    #pragma unroll
    for (int t = 0; t < 4; t++) {
        v[t] = *reinterpret_cast<const float4*>(xr + (size_t)(t * 32 + lane) * 4);
        s  += v[t].x + v[t].y + v[t].z + v[t].w;
        s2 += v[t].x * v[t].x + v[t].y * v[t].y + v[t].z * v[t].z + v[t].w * v[t].w;
    }
    #pragma unroll
    for (int o = 16; o > 0; o >>= 1) {
        s  += __shfl_xor_sync(0xffffffffu, s,  o);
        s2 += __shfl_xor_sync(0xffffffffu, s2, o);
    }
    const float mean = s * (1.f / DD);
    const float var  = s2 * (1.f / DD) - mean * mean;
    const float rstd = rsqrtf(var + EPS_LN);
    float* orow = out + (size_t)row * DD;
    #pragma unroll
    for (int t = 0; t < 4; t++) {
        int c = (t * 32 + lane) * 4;
        float4 gv = *reinterpret_cast<const float4*>(gw + c);
        float4 bv = *reinterpret_cast<const float4*>(bw + c);
        float4 r;
        r.x = (v[t].x - mean) * rstd * gv.x + bv.x;
        r.y = (v[t].y - mean) * rstd * gv.y + bv.y;
        r.z = (v[t].z - mean) * rstd * gv.z + bv.z;
        r.w = (v[t].w - mean) * rstd * gv.w + bv.w;
        *reinterpret_cast<float4*>(orow + c) = r;
        if (out16) {
            h4 o;
            o.a = __floats2half2_rn(r.x, r.y);
            o.b = __floats2half2_rn(r.z, r.w);
            *reinterpret_cast<h4*>(out16 + (size_t)row * DD + c) = o;
        }
    }
}

// ---------------- launch ----------------
extern "C" void kernel_launch(void* const* d_in, const int* in_sizes, int n_in,
                              void* d_out, int out_size)
{
    const float* src  = (const float*)d_in[0];
    const float* Wq   = (const float*)d_in[1];  const float* bq  = (const float*)d_in[2];
    const float* Wk   = (const float*)d_in[3];  const float* bk  = (const float*)d_in[4];
    const float* Wv   = (const float*)d_in[5];  const float* bv  = (const float*)d_in[6];
    const float* mat  = (const float*)d_in[7];
    const float* Wo   = (const float*)d_in[8];  const float* bo  = (const float*)d_in[9];
    const float* ln1g = (const float*)d_in[10]; const float* ln1b = (const float*)d_in[11];
    const float* W1   = (const float*)d_in[12]; const float* b1  = (const float*)d_in[13];
    const float* W2   = (const float*)d_in[14]; const float* b2  = (const float*)d_in[15];
    const float* ln2g = (const float*)d_in[16]; const float* ln2b = (const float*)d_in[17];

    float* y_out = (float*)d_out;
    float* scores_out = y_out + (size_t)NT * DD;

    __half *src16, *q16, *k16, *v16, *ao16, *x16, *ff16, *wt;
    float *t, *x;
    cudaGetSymbolAddress((void**)&src16, g_src16);
    cudaGetSymbolAddress((void**)&q16,  g_q16);
    cudaGetSymbolAddress((void**)&k16,  g_k16);
    cudaGetSymbolAddress((void**)&v16,  g_v16);
    cudaGetSymbolAddress((void**)&ao16, g_ao16);
    cudaGetSymbolAddress((void**)&x16,  g_x16);
    cudaGetSymbolAddress((void**)&ff16, g_ff16);
    cudaGetSymbolAddress((void**)&wt,   g_wt16);
    cudaGetSymbolAddress((void**)&t,    g_t);
    cudaGetSymbolAddress((void**)&x,    g_x);

    cudaFuncSetAttribute(qkv_kernel,     cudaFuncAttributeMaxDynamicSharedMemorySize, SMEM_GEMM);
    cudaFuncSetAttribute(gemm_kernel<1>, cudaFuncAttributeMaxDynamicSharedMemorySize, SMEM_GEMM);
    cudaFuncSetAttribute(gemm_kernel<2>, cudaFuncAttributeMaxDynamicSharedMemorySize, SMEM_GEMM);
    cudaFuncSetAttribute(attn_kernel,    cudaFuncAttributeMaxDynamicSharedMemorySize, SMEM_ATTN);

    // ---- prep: src->fp16, weights transpose+fp16 ----
    cvt16_kernel<<<(NT*DD/4 + 255)/256, 256>>>(src, src16, NT*DD/4);
    dim3 tb(32, 8);
    transpose4_kernel<<<dim3(DD/32, DD/32, 4), tb>>>(Wq, Wk, Wv, Wo, wt);
    transpose16_kernel<<<dim3(DFF/32, DD/32), tb>>>(W1, wt + WT_1, DD, DFF);
    transpose16_kernel<<<dim3(DD/32, DFF/32), tb>>>(W2, wt + WT_2, DFF, DD);

    dim3 gqkv(DD / 128, NT / 128, 3);   // (4, 192, 3)
    dim3 g512(DD / 128, NT / 128);      // (4, 192)
    dim3 gff (DFF / 128, NT / 128);     // (16, 192)

    qkv_kernel<<<gqkv, 256, SMEM_GEMM>>>(src16, wt, bq, bk, bv, q16, k16, v16);
    attn_kernel<<<BB * HH, 256, SMEM_ATTN>>>(q16, k16, v16, mat, scores_out, ao16);
    gemm_kernel<2><<<g512, 256, SMEM_GEMM>>>(ao16, wt + WT_O, bo, src, t, DD, DD);
    ln_kernel<<<NT / 8, 256>>>(t, ln1g, ln1b, x, x16);
    gemm_kernel<1><<<gff, 256, SMEM_GEMM>>>(x16, wt + WT_1, b1, nullptr, ff16, DFF, DD);
    gemm_kernel<2><<<g512, 256, SMEM_GEMM>>>(ff16, wt + WT_2, b2, x, t, DD, DFF);
    ln_kernel<<<NT / 8, 256>>>(t, ln2g, ln2b, y_out, nullptr);
}